// round 9
// baseline (speedup 1.0000x reference)
#include <cuda_runtime.h>
#include <cstdint>
#include <cstddef>

#define NN 100000
#define NE 1600000
#define F  64

// ---------------- scratch (static device globals; no allocation) -------------
static __device__ int g_mode;                               // 1 = int64 input, 0 = int32
static __device__ __align__(16) int   g_row [NE];
static __device__ __align__(16) int   g_col [NE];
static __device__ __align__(16) float g_deg [NN];
static __device__ __align__(16) float g_dinv[NN];
static __device__ __align__(16) float g_h1  [(size_t)NN * F];   // (x@W1) * dinv[i]  (pre-scaled)
static __device__ __align__(16) float g_agg1[(size_t)NN * F];   // aggregated layer-1
static __device__ __align__(16) float g_h2  [(size_t)NN * 2];   // (relu(agg1+b1)@W2) * dinv[i]
static __device__ __align__(16) float g_agg2[(size_t)NN * 2];   // aggregated logits

// ---------------- dtype detection --------------------------------------------
// int64 little-endian values in [0, NN) have zero high words at all odd int32
// positions. Random int32 edges make "1024 consecutive odd slots all zero"
// impossible (~(1e-5)^1024). One block, deterministic.
__global__ void k_detect(const int* __restrict__ ei32) {
    __shared__ int any_nz;
    if (threadIdx.x == 0) any_nz = 0;
    __syncthreads();
    int nz = 0;
    for (int s = threadIdx.x; s < 1024; s += blockDim.x)
        nz |= (ei32[2 * s + 1] != 0);
    if (nz) atomicOr(&any_nz, 1);
    __syncthreads();
    if (threadIdx.x == 0) g_mode = any_nz ? 0 : 1;
}

// ---------------- degree init ------------------------------------------------
__global__ void k_init_deg() {
    int i = blockIdx.x * blockDim.x + threadIdx.x;
    if (i < NN) g_deg[i] = 1.0f;  // self-loop
}

// ---------------- unpack edges (either dtype) + degree count -----------------
__global__ void __launch_bounds__(256) k_unpack(const int* __restrict__ ei32) {
    int e = blockIdx.x * blockDim.x + threadIdx.x;
    if (e >= NE) return;
    int r, c;
    if (g_mode) {                       // int64: low word at 2*pos
        r = ei32[2 * (size_t)e];
        c = ei32[2 * ((size_t)NE + e)];
    } else {                            // int32
        r = ei32[e];
        c = ei32[NE + e];
    }
    // safety clamp (valid inputs are always in range; protects vs. bad decode)
    if ((unsigned)r >= NN) r = 0;
    if ((unsigned)c >= NN) c = 0;
    g_row[e] = r;
    g_col[e] = c;
    atomicAdd(&g_deg[r], 1.0f);
}

__global__ void k_dinv() {
    int i = blockIdx.x * blockDim.x + threadIdx.x;
    if (i < NN) g_dinv[i] = rsqrtf(g_deg[i]);  // deg >= 1 always (self-loop)
}

// ---------------- layer 1 GEMM: h1 = (x @ W1) * dinv, agg1 init = h1 * dinv --
__global__ void __launch_bounds__(256) k_gemm1(const float* __restrict__ x,
                                               const float* __restrict__ W1) {
    __shared__ float ws[64 * 64];   // W1, row-major [k][j]
    __shared__ float xs[32 * 64];   // 32-row x tile
    int tid  = threadIdx.x;
    int row0 = blockIdx.x * 32;

    for (int i = tid; i < 4096; i += 256) ws[i] = W1[i];
    for (int i = tid; i < 512; i += 256) {          // 512 float4 = 32x64 floats
        int r = i >> 4, c4 = i & 15;
        int gr = row0 + r;
        float4 v = (gr < NN) ? ((const float4*)x)[(size_t)gr * 16 + c4]
                             : make_float4(0.f, 0.f, 0.f, 0.f);
        ((float4*)xs)[i] = v;
    }
    __syncthreads();

    int r = tid >> 3, cg = tid & 7;                 // 8 output cols per thread
    float acc[8] = {0.f, 0.f, 0.f, 0.f, 0.f, 0.f, 0.f, 0.f};
    #pragma unroll
    for (int k = 0; k < 64; k++) {
        float xv = xs[r * 64 + k];
        #pragma unroll
        for (int j = 0; j < 8; j++)
            acc[j] = fmaf(xv, ws[k * 64 + cg * 8 + j], acc[j]);
    }

    int gr = row0 + r;
    if (gr < NN) {
        float di = g_dinv[gr];
        float o[8];
        #pragma unroll
        for (int j = 0; j < 8; j++) o[j] = acc[j] * di;        // pre-scale by dinv[i]
        float4* hp = (float4*)(g_h1 + (size_t)gr * F + cg * 8);
        hp[0] = make_float4(o[0], o[1], o[2], o[3]);
        hp[1] = make_float4(o[4], o[5], o[6], o[7]);
        float4* ap = (float4*)(g_agg1 + (size_t)gr * F + cg * 8);
        ap[0] = make_float4(o[0] * di, o[1] * di, o[2] * di, o[3] * di);  // self-loop
        ap[1] = make_float4(o[4] * di, o[5] * di, o[6] * di, o[7] * di);
    }
}

// ---------------- layer 1 edge scatter: agg1[row] += h1[col] * dinv[row] -----
// 16 lanes per edge, float4 per lane, vector RED (no return).
__global__ void __launch_bounds__(256) k_scat1() {
    int g = blockIdx.x * blockDim.x + threadIdx.x;
    int e = g >> 4;
    if (e >= NE) return;
    int lane = g & 15;
    int r = g_row[e];
    int c = g_col[e];
    float dr = g_dinv[r];
    float4 v = *(const float4*)(g_h1 + (size_t)c * F + (lane << 2));
    float a0 = v.x * dr, a1 = v.y * dr, a2 = v.z * dr, a3 = v.w * dr;
    float* p = g_agg1 + (size_t)r * F + (lane << 2);
    asm volatile("red.global.add.v4.f32 [%0], {%1, %2, %3, %4};"
                 :: "l"(p), "f"(a0), "f"(a1), "f"(a2), "f"(a3) : "memory");
}

// ---------------- layer 2: z = relu(agg1+b1); h2 = (z@W2)*dinv; agg2 init ----
__global__ void __launch_bounds__(256) k_layer2(const float* __restrict__ b1,
                                                const float* __restrict__ W2) {
    int i = blockIdx.x * blockDim.x + threadIdx.x;
    if (i >= NN) return;
    float di = g_dinv[i];
    float acc0 = 0.f, acc1 = 0.f;
    const float4* a = (const float4*)(g_agg1 + (size_t)i * F);
    #pragma unroll
    for (int k4 = 0; k4 < 16; k4++) {
        float4 v = a[k4];
        int k = k4 * 4;
        float z0 = fmaxf(v.x + __ldg(b1 + k + 0), 0.f);
        float z1 = fmaxf(v.y + __ldg(b1 + k + 1), 0.f);
        float z2 = fmaxf(v.z + __ldg(b1 + k + 2), 0.f);
        float z3 = fmaxf(v.w + __ldg(b1 + k + 3), 0.f);
        acc0 = fmaf(z0, __ldg(W2 + (k + 0) * 2 + 0), acc0);
        acc1 = fmaf(z0, __ldg(W2 + (k + 0) * 2 + 1), acc1);
        acc0 = fmaf(z1, __ldg(W2 + (k + 1) * 2 + 0), acc0);
        acc1 = fmaf(z1, __ldg(W2 + (k + 1) * 2 + 1), acc1);
        acc0 = fmaf(z2, __ldg(W2 + (k + 2) * 2 + 0), acc0);
        acc1 = fmaf(z2, __ldg(W2 + (k + 2) * 2 + 1), acc1);
        acc0 = fmaf(z3, __ldg(W2 + (k + 3) * 2 + 0), acc0);
        acc1 = fmaf(z3, __ldg(W2 + (k + 3) * 2 + 1), acc1);
    }
    float h0 = acc0 * di, h1v = acc1 * di;           // pre-scale by dinv[i]
    *(float2*)(g_h2   + (size_t)i * 2) = make_float2(h0, h1v);
    *(float2*)(g_agg2 + (size_t)i * 2) = make_float2(h0 * di, h1v * di);  // self-loop
}

// ---------------- layer 2 edge scatter: agg2[row] += h2[col] * dinv[row] -----
__global__ void __launch_bounds__(256) k_scat2() {
    int e = blockIdx.x * blockDim.x + threadIdx.x;
    if (e >= NE) return;
    int r = g_row[e];
    int c = g_col[e];
    float dr = g_dinv[r];
    float2 v = *(const float2*)(g_h2 + (size_t)c * 2);
    float a0 = v.x * dr, a1 = v.y * dr;
    float* p = g_agg2 + (size_t)r * 2;
    asm volatile("red.global.add.v2.f32 [%0], {%1, %2};"
                 :: "l"(p), "f"(a0), "f"(a1) : "memory");
}

// ---------------- softmax over 2 classes -------------------------------------
__global__ void __launch_bounds__(256) k_softmax(const float* __restrict__ b2,
                                                 float* __restrict__ out) {
    int i = blockIdx.x * blockDim.x + threadIdx.x;
    if (i >= NN) return;
    float2 l = *(const float2*)(g_agg2 + (size_t)i * 2);
    float l0 = l.x + b2[0], l1 = l.y + b2[1];
    float m  = fmaxf(l0, l1);
    float e0 = expf(l0 - m), e1 = expf(l1 - m);
    float s  = 1.0f / (e0 + e1);
    *(float2*)(out + (size_t)i * 2) = make_float2(e0 * s, e1 * s);
}

// ---------------- launch ------------------------------------------------------
extern "C" void kernel_launch(void* const* d_in, const int* in_sizes, int n_in,
                              void* d_out, int out_size) {
    const float* x    = (const float*)d_in[0];       // [NN, 64]
    const int*   ei32 = (const int*)d_in[1];         // [2, NE] int32 (or int64 viewed as int32)
    const float* W1   = (const float*)d_in[2];       // [64, 64]
    const float* b1   = (const float*)d_in[3];       // [64]
    const float* W2   = (const float*)d_in[4];       // [64, 2]
    const float* b2   = (const float*)d_in[5];       // [2]
    float*       out  = (float*)d_out;               // [NN, 2]
    (void)in_sizes; (void)n_in; (void)out_size;

    k_detect  <<<1, 256>>>(ei32);
    k_init_deg<<<(NN + 255) / 256, 256>>>();
    k_unpack  <<<(NE + 255) / 256, 256>>>(ei32);
    k_dinv    <<<(NN + 255) / 256, 256>>>();
    k_gemm1   <<<(NN + 31) / 32, 256>>>(x, W1);
    k_scat1   <<<(NE * 16 + 255) / 256, 256>>>();    // 25.6M threads, 16/edge
    k_layer2  <<<(NN + 255) / 256, 256>>>(b1, W2);
    k_scat2   <<<(NE + 255) / 256, 256>>>();
    k_softmax <<<(NN + 255) / 256, 256>>>(b2, out);
}

// round 10
// speedup vs baseline: 1.2804x; 1.2804x over previous
#include <cuda_runtime.h>
#include <cstdint>
#include <cstddef>

#define NN 100000
#define NE 1600000
#define F  64
#define SCAN_B 1024
#define NBLK ((NN + SCAN_B - 1) / SCAN_B)   // 98

// ---------------- scratch (static device globals; no allocation) -------------
static __device__ int g_mode;                       // 1 = int64 input, 0 = int32
static __device__ __align__(16) int   g_row [NE];
static __device__ __align__(16) int   g_col [NE];
static __device__ __align__(16) int   g_ecol[NE];   // CSR column array
static __device__ __align__(16) int   g_cnt [NN];   // neighbor count (excl. self)
static __device__ __align__(16) int   g_off [NN];   // CSR row offsets (exclusive)
static __device__ __align__(16) int   g_fill[NN];   // fill cursors
static __device__ __align__(16) int   g_bsum[NBLK];
static __device__ __align__(16) int   g_bscan[NBLK];
static __device__ __align__(16) float g_dinv[NN];
static __device__ __align__(16) float g_h1 [(size_t)NN * F]; // (x@W1)*dinv[i]
static __device__ __align__(16) float g_h2 [(size_t)NN * 2]; // (relu(.)@W2)*dinv[i]

// ---------------- dtype detection --------------------------------------------
__global__ void k_detect(const int* __restrict__ ei32) {
    __shared__ int any_nz;
    if (threadIdx.x == 0) any_nz = 0;
    __syncthreads();
    int nz = 0;
    for (int s = threadIdx.x; s < 1024; s += blockDim.x)
        nz |= (ei32[2 * s + 1] != 0);
    if (nz) atomicOr(&any_nz, 1);
    __syncthreads();
    if (threadIdx.x == 0) g_mode = any_nz ? 0 : 1;
}

__global__ void k_zero_cnt() {
    int i = blockIdx.x * blockDim.x + threadIdx.x;
    if (i < NN) g_cnt[i] = 0;
}

// ---------------- unpack edges (either dtype) + degree count -----------------
__global__ void __launch_bounds__(256) k_unpack(const int* __restrict__ ei32) {
    int e = blockIdx.x * blockDim.x + threadIdx.x;
    if (e >= NE) return;
    int r, c;
    if (g_mode) {                       // int64: low word at 2*pos
        r = ei32[2 * (size_t)e];
        c = ei32[2 * ((size_t)NE + e)];
    } else {                            // int32
        r = ei32[e];
        c = ei32[NE + e];
    }
    if ((unsigned)r >= NN) r = 0;       // safety clamp
    if ((unsigned)c >= NN) c = 0;
    g_row[e] = r;
    g_col[e] = c;
    atomicAdd(&g_cnt[r], 1);
}

__global__ void k_dinv() {
    int i = blockIdx.x * blockDim.x + threadIdx.x;
    if (i < NN) g_dinv[i] = rsqrtf((float)(g_cnt[i] + 1));  // +1 self-loop
}

// ---------------- prefix scan (3-phase) --------------------------------------
__global__ void __launch_bounds__(SCAN_B) k_scan1() {
    __shared__ int s[SCAN_B];
    int tid = threadIdx.x;
    int i = blockIdx.x * SCAN_B + tid;
    int v = (i < NN) ? g_cnt[i] : 0;
    s[tid] = v;
    __syncthreads();
    #pragma unroll
    for (int d = 1; d < SCAN_B; d <<= 1) {
        int t = (tid >= d) ? s[tid - d] : 0;
        __syncthreads();
        s[tid] += t;
        __syncthreads();
    }
    if (i < NN) g_off[i] = s[tid] - v;            // exclusive
    if (tid == SCAN_B - 1) g_bsum[blockIdx.x] = s[tid];
}

__global__ void __launch_bounds__(128) k_scan2() {
    __shared__ int s[128];
    int tid = threadIdx.x;
    int v = (tid < NBLK) ? g_bsum[tid] : 0;
    s[tid] = v;
    __syncthreads();
    #pragma unroll
    for (int d = 1; d < 128; d <<= 1) {
        int t = (tid >= d) ? s[tid - d] : 0;
        __syncthreads();
        s[tid] += t;
        __syncthreads();
    }
    if (tid < NBLK) g_bscan[tid] = s[tid] - v;    // exclusive
}

__global__ void k_scan3() {
    int i = blockIdx.x * blockDim.x + threadIdx.x;
    if (i < NN) {
        g_off[i] += g_bscan[i >> 10];
        g_fill[i] = 0;
    }
}

// ---------------- CSR fill ----------------------------------------------------
__global__ void __launch_bounds__(256) k_fill() {
    int e = blockIdx.x * blockDim.x + threadIdx.x;
    if (e >= NE) return;
    int r = g_row[e];
    int pos = g_off[r] + atomicAdd(&g_fill[r], 1);
    g_ecol[pos] = g_col[e];
}

// ---------------- layer 1 GEMM: h1 = (x @ W1) * dinv --------------------------
__global__ void __launch_bounds__(256) k_gemm1(const float* __restrict__ x,
                                               const float* __restrict__ W1) {
    __shared__ float ws[64 * 64];
    __shared__ float xs[32 * 64];
    int tid  = threadIdx.x;
    int row0 = blockIdx.x * 32;

    for (int i = tid; i < 4096; i += 256) ws[i] = W1[i];
    for (int i = tid; i < 512; i += 256) {
        int r = i >> 4, c4 = i & 15;
        int gr = row0 + r;
        float4 v = (gr < NN) ? ((const float4*)x)[(size_t)gr * 16 + c4]
                             : make_float4(0.f, 0.f, 0.f, 0.f);
        ((float4*)xs)[i] = v;
    }
    __syncthreads();

    int r = tid >> 3, cg = tid & 7;
    float acc[8] = {0.f, 0.f, 0.f, 0.f, 0.f, 0.f, 0.f, 0.f};
    #pragma unroll
    for (int k = 0; k < 64; k++) {
        float xv = xs[r * 64 + k];
        #pragma unroll
        for (int j = 0; j < 8; j++)
            acc[j] = fmaf(xv, ws[k * 64 + cg * 8 + j], acc[j]);
    }

    int gr = row0 + r;
    if (gr < NN) {
        float di = g_dinv[gr];
        float4* hp = (float4*)(g_h1 + (size_t)gr * F + cg * 8);
        hp[0] = make_float4(acc[0] * di, acc[1] * di, acc[2] * di, acc[3] * di);
        hp[1] = make_float4(acc[4] * di, acc[5] * di, acc[6] * di, acc[7] * di);
    }
}

// ---------------- fused gather1 + ReLU + W2 -----------------------------------
// 16 lanes per row. agg1[i] = dinv[i]*(h1s[i] + sum_nb h1s[c]); z = relu(agg1+b1);
// h2s[i] = (z @ W2) * dinv[i]. agg1 never touches memory.
__global__ void __launch_bounds__(256) k_gather1(const float* __restrict__ b1,
                                                 const float* __restrict__ W2) {
    int g = blockIdx.x * blockDim.x + threadIdx.x;
    int i = g >> 4;
    if (i >= NN) return;
    int lane = g & 15;
    int f0 = lane << 2;

    float dr  = g_dinv[i];
    int base  = g_off[i];
    int deg   = g_cnt[i];

    float4 acc = *(const float4*)(g_h1 + (size_t)i * F + f0);   // self term
    const int* ep = g_ecol + base;
    int j = 0;
    for (; j + 4 <= deg; j += 4) {                              // ILP: 4 gathers in flight
        int c0 = ep[j], c1 = ep[j+1], c2 = ep[j+2], c3 = ep[j+3];
        float4 v0 = *(const float4*)(g_h1 + (size_t)c0 * F + f0);
        float4 v1 = *(const float4*)(g_h1 + (size_t)c1 * F + f0);
        float4 v2 = *(const float4*)(g_h1 + (size_t)c2 * F + f0);
        float4 v3 = *(const float4*)(g_h1 + (size_t)c3 * F + f0);
        acc.x += v0.x + v1.x + v2.x + v3.x;
        acc.y += v0.y + v1.y + v2.y + v3.y;
        acc.z += v0.z + v1.z + v2.z + v3.z;
        acc.w += v0.w + v1.w + v2.w + v3.w;
    }
    for (; j < deg; j++) {
        int c = ep[j];
        float4 v = *(const float4*)(g_h1 + (size_t)c * F + f0);
        acc.x += v.x; acc.y += v.y; acc.z += v.z; acc.w += v.w;
    }

    // z = relu(dr*acc + b1[f]); partial dot with W2
    float z0 = fmaxf(fmaf(dr, acc.x, __ldg(b1 + f0 + 0)), 0.f);
    float z1 = fmaxf(fmaf(dr, acc.y, __ldg(b1 + f0 + 1)), 0.f);
    float z2 = fmaxf(fmaf(dr, acc.z, __ldg(b1 + f0 + 2)), 0.f);
    float z3 = fmaxf(fmaf(dr, acc.w, __ldg(b1 + f0 + 3)), 0.f);
    float a0 = z0 * __ldg(W2 + (f0 + 0) * 2 + 0) + z1 * __ldg(W2 + (f0 + 1) * 2 + 0)
             + z2 * __ldg(W2 + (f0 + 2) * 2 + 0) + z3 * __ldg(W2 + (f0 + 3) * 2 + 0);
    float a1 = z0 * __ldg(W2 + (f0 + 0) * 2 + 1) + z1 * __ldg(W2 + (f0 + 1) * 2 + 1)
             + z2 * __ldg(W2 + (f0 + 2) * 2 + 1) + z3 * __ldg(W2 + (f0 + 3) * 2 + 1);

    #pragma unroll
    for (int m = 1; m < 16; m <<= 1) {          // reduce within 16-lane group
        a0 += __shfl_xor_sync(0xffffffffu, a0, m);
        a1 += __shfl_xor_sync(0xffffffffu, a1, m);
    }
    if (lane == 0)
        *(float2*)(g_h2 + (size_t)i * 2) = make_float2(a0 * dr, a1 * dr);
}

// ---------------- fused gather2 + softmax -------------------------------------
__global__ void __launch_bounds__(256) k_gather2(const float* __restrict__ b2,
                                                 float* __restrict__ out) {
    int i = blockIdx.x * blockDim.x + threadIdx.x;
    if (i >= NN) return;
    float dr = g_dinv[i];
    int base = g_off[i];
    int deg  = g_cnt[i];

    float2 a = *(const float2*)(g_h2 + (size_t)i * 2);   // self term
    const int* ep = g_ecol + base;
    int j = 0;
    for (; j + 4 <= deg; j += 4) {
        int c0 = ep[j], c1 = ep[j+1], c2 = ep[j+2], c3 = ep[j+3];
        float2 v0 = *(const float2*)(g_h2 + (size_t)c0 * 2);
        float2 v1 = *(const float2*)(g_h2 + (size_t)c1 * 2);
        float2 v2 = *(const float2*)(g_h2 + (size_t)c2 * 2);
        float2 v3 = *(const float2*)(g_h2 + (size_t)c3 * 2);
        a.x += v0.x + v1.x + v2.x + v3.x;
        a.y += v0.y + v1.y + v2.y + v3.y;
    }
    for (; j < deg; j++) {
        int c = ep[j];
        float2 v = *(const float2*)(g_h2 + (size_t)c * 2);
        a.x += v.x; a.y += v.y;
    }

    float l0 = fmaf(dr, a.x, __ldg(b2 + 0));
    float l1 = fmaf(dr, a.y, __ldg(b2 + 1));
    float m  = fmaxf(l0, l1);
    float e0 = expf(l0 - m), e1 = expf(l1 - m);
    float s  = 1.0f / (e0 + e1);
    *(float2*)(out + (size_t)i * 2) = make_float2(e0 * s, e1 * s);
}

// ---------------- launch ------------------------------------------------------
extern "C" void kernel_launch(void* const* d_in, const int* in_sizes, int n_in,
                              void* d_out, int out_size) {
    const float* x    = (const float*)d_in[0];   // [NN, 64]
    const int*   ei32 = (const int*)d_in[1];     // [2, NE] int32 (or int64 viewed as int32)
    const float* W1   = (const float*)d_in[2];   // [64, 64]
    const float* b1   = (const float*)d_in[3];   // [64]
    const float* W2   = (const float*)d_in[4];   // [64, 2]
    const float* b2   = (const float*)d_in[5];   // [2]
    float*       out  = (float*)d_out;           // [NN, 2]
    (void)in_sizes; (void)n_in; (void)out_size;

    k_detect  <<<1, 256>>>(ei32);
    k_zero_cnt<<<(NN + 255) / 256, 256>>>();
    k_unpack  <<<(NE + 255) / 256, 256>>>(ei32);
    k_dinv    <<<(NN + 255) / 256, 256>>>();
    k_scan1   <<<NBLK, SCAN_B>>>();
    k_scan2   <<<1, 128>>>();
    k_scan3   <<<(NN + 255) / 256, 256>>>();
    k_fill    <<<(NE + 255) / 256, 256>>>();
    k_gemm1   <<<(NN + 31) / 32, 256>>>(x, W1);
    k_gather1 <<<(NN * 16 + 255) / 256, 256>>>(b1, W2);
    k_gather2 <<<(NN + 255) / 256, 256>>>(b2, out);
}

// round 12
// speedup vs baseline: 1.2970x; 1.0130x over previous
#include <cuda_runtime.h>
#include <cstdint>
#include <cstddef>

#define NN 100000
#define NE 1600000
#define F  64
#define SCAN_B 1024
#define NBLK ((NN + SCAN_B - 1) / SCAN_B)   // 98

// ---------------- scratch (static device globals; no allocation) -------------
static __device__ int g_mode;                       // 1 = int64 input, 0 = int32
static __device__ __align__(16) int   g_ecol[NE];   // CSR column array
static __device__ __align__(16) int   g_cnt [NN];   // neighbor count (excl. self)
static __device__ __align__(16) int   g_off [NN];   // CSR row offsets (exclusive)
static __device__ __align__(16) int   g_fill[NN];   // fill cursors
static __device__ __align__(16) int   g_bsum[NBLK];
static __device__ __align__(16) int   g_bscan[NBLK];
static __device__ __align__(16) float g_dinv[NN];
static __device__ __align__(16) float g_h1 [(size_t)NN * F]; // (x@W1)*dinv[i]
static __device__ __align__(16) float g_h2 [(size_t)NN * 2]; // (relu(.)@W2)*dinv[i]

// ---------------- init: dtype detect (block 0) + zero counts ------------------
// int64 little-endian values in [0, NN) have zero high words at all odd int32
// positions; 1024 consecutive zero odd-slots is impossible for random int32.
__global__ void k_init(const int* __restrict__ ei32) {
    int i = blockIdx.x * blockDim.x + threadIdx.x;
    if (i < NN) g_cnt[i] = 0;
    if (blockIdx.x == 0) {
        __shared__ int any_nz;
        if (threadIdx.x == 0) any_nz = 0;
        __syncthreads();
        int nz = 0;
        for (int s = threadIdx.x; s < 1024; s += blockDim.x)
            nz |= (ei32[2 * s + 1] != 0);
        if (nz) atomicOr(&any_nz, 1);
        __syncthreads();
        if (threadIdx.x == 0) g_mode = any_nz ? 0 : 1;
    }
}

// ---------------- degree count (reads row half only) --------------------------
__global__ void __launch_bounds__(256) k_unpack(const int* __restrict__ ei32) {
    int e = blockIdx.x * blockDim.x + threadIdx.x;
    if (e >= NE) return;
    int r = g_mode ? ei32[2 * (size_t)e] : ei32[e];
    if ((unsigned)r >= NN) r = 0;       // safety clamp
    atomicAdd(&g_cnt[r], 1);
}

// ---------------- prefix scan (3-phase) + dinv --------------------------------
__global__ void __launch_bounds__(SCAN_B) k_scan1() {
    __shared__ int s[SCAN_B];
    int tid = threadIdx.x;
    int i = blockIdx.x * SCAN_B + tid;
    int v = (i < NN) ? g_cnt[i] : 0;
    if (i < NN) g_dinv[i] = rsqrtf((float)(v + 1));  // +1 self-loop
    s[tid] = v;
    __syncthreads();
    #pragma unroll
    for (int d = 1; d < SCAN_B; d <<= 1) {
        int t = (tid >= d) ? s[tid - d] : 0;
        __syncthreads();
        s[tid] += t;
        __syncthreads();
    }
    if (i < NN) g_off[i] = s[tid] - v;            // exclusive
    if (tid == SCAN_B - 1) g_bsum[blockIdx.x] = s[tid];
}

__global__ void __launch_bounds__(128) k_scan2() {
    __shared__ int s[128];
    int tid = threadIdx.x;
    int v = (tid < NBLK) ? g_bsum[tid] : 0;
    s[tid] = v;
    __syncthreads();
    #pragma unroll
    for (int d = 1; d < 128; d <<= 1) {
        int t = (tid >= d) ? s[tid - d] : 0;
        __syncthreads();
        s[tid] += t;
        __syncthreads();
    }
    if (tid < NBLK) g_bscan[tid] = s[tid] - v;    // exclusive
}

__global__ void k_scan3() {
    int i = blockIdx.x * blockDim.x + threadIdx.x;
    if (i < NN) {
        g_off[i] += g_bscan[i >> 10];
        g_fill[i] = 0;
    }
}

// ---------------- CSR fill (re-decodes edges; no g_row/g_col arrays) ----------
__global__ void __launch_bounds__(256) k_fill(const int* __restrict__ ei32) {
    int e = blockIdx.x * blockDim.x + threadIdx.x;
    if (e >= NE) return;
    int r, c;
    if (g_mode) {
        r = ei32[2 * (size_t)e];
        c = ei32[2 * ((size_t)NE + e)];
    } else {
        r = ei32[e];
        c = ei32[NE + e];
    }
    if ((unsigned)r >= NN) r = 0;       // identical clamp to k_unpack
    if ((unsigned)c >= NN) c = 0;
    int pos = g_off[r] + atomicAdd(&g_fill[r], 1);
    g_ecol[pos] = c;
}

// ---------------- layer 1 GEMM: h1 = (x @ W1) * dinv --------------------------
__global__ void __launch_bounds__(256) k_gemm1(const float* __restrict__ x,
                                               const float* __restrict__ W1) {
    __shared__ float ws[64 * 64];
    __shared__ float xs[32 * 64];
    int tid  = threadIdx.x;
    int row0 = blockIdx.x * 32;

    for (int i = tid; i < 4096; i += 256) ws[i] = W1[i];
    for (int i = tid; i < 512; i += 256) {
        int r = i >> 4, c4 = i & 15;
        int gr = row0 + r;
        float4 v = (gr < NN) ? ((const float4*)x)[(size_t)gr * 16 + c4]
                             : make_float4(0.f, 0.f, 0.f, 0.f);
        ((float4*)xs)[i] = v;
    }
    __syncthreads();

    int r = tid >> 3, cg = tid & 7;
    float acc[8] = {0.f, 0.f, 0.f, 0.f, 0.f, 0.f, 0.f, 0.f};
    #pragma unroll
    for (int k = 0; k < 64; k++) {
        float xv = xs[r * 64 + k];
        #pragma unroll
        for (int j = 0; j < 8; j++)
            acc[j] = fmaf(xv, ws[k * 64 + cg * 8 + j], acc[j]);
    }

    int gr = row0 + r;
    if (gr < NN) {
        float di = g_dinv[gr];
        float4* hp = (float4*)(g_h1 + (size_t)gr * F + cg * 8);
        hp[0] = make_float4(acc[0] * di, acc[1] * di, acc[2] * di, acc[3] * di);
        hp[1] = make_float4(acc[4] * di, acc[5] * di, acc[6] * di, acc[7] * di);
    }
}

// ---------------- fused gather1 + ReLU + W2 -----------------------------------
// 16 lanes per row, unroll 8 (8 LDG.128 in flight), dual accumulators.
__global__ void __launch_bounds__(256) k_gather1(const float* __restrict__ b1,
                                                 const float* __restrict__ W2) {
    int g = blockIdx.x * blockDim.x + threadIdx.x;
    int i = g >> 4;
    if (i >= NN) return;
    int lane = g & 15;
    int f0 = lane << 2;

    float dr  = g_dinv[i];
    int base  = g_off[i];
    int deg   = g_cnt[i];
    const int* ep = g_ecol + base;

    float4 accA = *(const float4*)(g_h1 + (size_t)i * F + f0);   // self term
    float4 accB = make_float4(0.f, 0.f, 0.f, 0.f);

    int j = 0;
    for (; j + 8 <= deg; j += 8) {
        int c0 = ep[j+0], c1 = ep[j+1], c2 = ep[j+2], c3 = ep[j+3];
        int c4 = ep[j+4], c5 = ep[j+5], c6 = ep[j+6], c7 = ep[j+7];
        float4 v0 = *(const float4*)(g_h1 + (size_t)c0 * F + f0);
        float4 v1 = *(const float4*)(g_h1 + (size_t)c1 * F + f0);
        float4 v2 = *(const float4*)(g_h1 + (size_t)c2 * F + f0);
        float4 v3 = *(const float4*)(g_h1 + (size_t)c3 * F + f0);
        float4 v4 = *(const float4*)(g_h1 + (size_t)c4 * F + f0);
        float4 v5 = *(const float4*)(g_h1 + (size_t)c5 * F + f0);
        float4 v6 = *(const float4*)(g_h1 + (size_t)c6 * F + f0);
        float4 v7 = *(const float4*)(g_h1 + (size_t)c7 * F + f0);
        accA.x += (v0.x + v1.x) + (v2.x + v3.x);
        accA.y += (v0.y + v1.y) + (v2.y + v3.y);
        accA.z += (v0.z + v1.z) + (v2.z + v3.z);
        accA.w += (v0.w + v1.w) + (v2.w + v3.w);
        accB.x += (v4.x + v5.x) + (v6.x + v7.x);
        accB.y += (v4.y + v5.y) + (v6.y + v7.y);
        accB.z += (v4.z + v5.z) + (v6.z + v7.z);
        accB.w += (v4.w + v5.w) + (v6.w + v7.w);
    }
    for (; j + 4 <= deg; j += 4) {
        int c0 = ep[j+0], c1 = ep[j+1], c2 = ep[j+2], c3 = ep[j+3];
        float4 v0 = *(const float4*)(g_h1 + (size_t)c0 * F + f0);
        float4 v1 = *(const float4*)(g_h1 + (size_t)c1 * F + f0);
        float4 v2 = *(const float4*)(g_h1 + (size_t)c2 * F + f0);
        float4 v3 = *(const float4*)(g_h1 + (size_t)c3 * F + f0);
        accA.x += (v0.x + v1.x) + (v2.x + v3.x);
        accA.y += (v0.y + v1.y) + (v2.y + v3.y);
        accA.z += (v0.z + v1.z) + (v2.z + v3.z);
        accA.w += (v0.w + v1.w) + (v2.w + v3.w);
    }
    for (; j < deg; j++) {
        int c = ep[j];
        float4 v = *(const float4*)(g_h1 + (size_t)c * F + f0);
        accB.x += v.x; accB.y += v.y; accB.z += v.z; accB.w += v.w;
    }
    float4 acc = make_float4(accA.x + accB.x, accA.y + accB.y,
                             accA.z + accB.z, accA.w + accB.w);

    // z = relu(dr*acc + b1[f]); partial dot with W2
    float z0 = fmaxf(fmaf(dr, acc.x, __ldg(b1 + f0 + 0)), 0.f);
    float z1 = fmaxf(fmaf(dr, acc.y, __ldg(b1 + f0 + 1)), 0.f);
    float z2 = fmaxf(fmaf(dr, acc.z, __ldg(b1 + f0 + 2)), 0.f);
    float z3 = fmaxf(fmaf(dr, acc.w, __ldg(b1 + f0 + 3)), 0.f);
    float a0 = z0 * __ldg(W2 + (f0 + 0) * 2 + 0) + z1 * __ldg(W2 + (f0 + 1) * 2 + 0)
             + z2 * __ldg(W2 + (f0 + 2) * 2 + 0) + z3 * __ldg(W2 + (f0 + 3) * 2 + 0);
    float a1 = z0 * __ldg(W2 + (f0 + 0) * 2 + 1) + z1 * __ldg(W2 + (f0 + 1) * 2 + 1)
             + z2 * __ldg(W2 + (f0 + 2) * 2 + 1) + z3 * __ldg(W2 + (f0 + 3) * 2 + 1);

    #pragma unroll
    for (int m = 1; m < 16; m <<= 1) {          // reduce within 16-lane group
        a0 += __shfl_xor_sync(0xffffffffu, a0, m);
        a1 += __shfl_xor_sync(0xffffffffu, a1, m);
    }
    if (lane == 0)
        *(float2*)(g_h2 + (size_t)i * 2) = make_float2(a0 * dr, a1 * dr);
}

// ---------------- fused gather2 + softmax (4 lanes/row) -----------------------
__global__ void __launch_bounds__(256) k_gather2(const float* __restrict__ b2,
                                                 float* __restrict__ out) {
    int g = blockIdx.x * blockDim.x + threadIdx.x;
    int i = g >> 2;
    if (i >= NN) return;
    int lane = g & 3;

    float dr = g_dinv[i];
    int base = g_off[i];
    int deg  = g_cnt[i];
    const int* ep = g_ecol + base;

    float ax = 0.f, ay = 0.f;
    for (int j = lane; j < deg; j += 4) {
        int c = ep[j];
        float2 v = *(const float2*)(g_h2 + (size_t)c * 2);
        ax += v.x; ay += v.y;
    }
    #pragma unroll
    for (int m = 1; m < 4; m <<= 1) {
        ax += __shfl_xor_sync(0xffffffffu, ax, m);
        ay += __shfl_xor_sync(0xffffffffu, ay, m);
    }
    if (lane == 0) {
        float2 self = *(const float2*)(g_h2 + (size_t)i * 2);
        float l0 = fmaf(dr, ax + self.x, __ldg(b2 + 0));
        float l1 = fmaf(dr, ay + self.y, __ldg(b2 + 1));
        float m  = fmaxf(l0, l1);
        float e0 = expf(l0 - m), e1 = expf(l1 - m);
        float s  = 1.0f / (e0 + e1);
        *(float2*)(out + (size_t)i * 2) = make_float2(e0 * s, e1 * s);
    }
}

// ---------------- launch ------------------------------------------------------
extern "C" void kernel_launch(void* const* d_in, const int* in_sizes, int n_in,
                              void* d_out, int out_size) {
    const float* x    = (const float*)d_in[0];   // [NN, 64]
    const int*   ei32 = (const int*)d_in[1];     // [2, NE] int32 (or int64 viewed as int32)
    const float* W1   = (const float*)d_in[2];   // [64, 64]
    const float* b1   = (const float*)d_in[3];   // [64]
    const float* W2   = (const float*)d_in[4];   // [64, 2]
    const float* b2   = (const float*)d_in[5];   // [2]
    float*       out  = (float*)d_out;           // [NN, 2]
    (void)in_sizes; (void)n_in; (void)out_size;

    k_init    <<<(NN + 255) / 256, 256>>>(ei32);
    k_unpack  <<<(NE + 255) / 256, 256>>>(ei32);
    k_scan1   <<<NBLK, SCAN_B>>>();
    k_scan2   <<<1, 128>>>();
    k_scan3   <<<(NN + 255) / 256, 256>>>();
    k_fill    <<<(NE + 255) / 256, 256>>>(ei32);
    k_gemm1   <<<(NN + 31) / 32, 256>>>(x, W1);
    k_gather1 <<<(NN * 16 + 255) / 256, 256>>>(b1, W2);
    k_gather2 <<<(NN * 4 + 255) / 256, 256>>>(b2, out);
}